// round 14
// baseline (speedup 1.0000x reference)
#include <cuda_runtime.h>
#include <math.h>

#define Bn 16
#define Hn 512
#define Wn 512
#define HW (Hn*Wn)
#define NBLK 64
#define BLKS_PER_IMG 128
#define TOTAL_LBP_BLOCKS (8*16*Bn)

// ---------------- scratch ----------------
__device__ unsigned char g_code[(size_t)Bn*HW];
__device__ float g_partial[Bn*BLKS_PER_IMG*4];   // r,g,b,maxcode per 64x32 tile
__device__ float g_scale[Bn*3];
__device__ float g_invmx[Bn];
__device__ unsigned long long g_wpad[225];       // padded weight pairs + bias
__device__ int g_ctr;                            // last-block ticket (reset each run)

__constant__ unsigned long long c_wp[225];       // [(c*7+ky)*8 + j], [224]=bias
__constant__ float c_d4[8] = { 0.35355339f,-0.35355339f,-0.35355339f, 0.35355339f,
                               0.35355339f,-0.35355339f,-0.35355339f, 0.35355339f };
__constant__ float c_d3[8] = { 0.41573481f,-0.09754516f,-0.49039264f,-0.27778512f,
                               0.27778512f, 0.49039264f, 0.09754516f,-0.41573481f };

// ---- packed f32x2 helpers ----
__device__ __forceinline__ unsigned long long pk2(float lo, float hi) {
    unsigned long long d;
    asm("mov.b64 %0, {%1, %2};" : "=l"(d) : "f"(lo), "f"(hi));
    return d;
}
__device__ __forceinline__ unsigned long long ffma2(unsigned long long a,
                                                    unsigned long long b,
                                                    unsigned long long c) {
    unsigned long long d;
    asm("fma.rn.f32x2 %0, %1, %2, %3;" : "=l"(d) : "l"(a), "l"(b), "l"(c));
    return d;
}
__device__ __forceinline__ void unpk2(unsigned long long v, float& lo, float& hi) {
    asm("mov.b64 {%0, %1}, %2;" : "=f"(lo), "=f"(hi) : "l"(v));
}

// ---------------- K1: gray + LBP + partials, fused final reduction ---------
// 256 threads, 64x32 tile, grid (8,16,B). smem col c <-> x = bx*64-4+c.
__global__ void __launch_bounds__(256) k_lbp(const float* __restrict__ frame,
                                             const float* __restrict__ ca_w1,
                                             const float* __restrict__ ca_w2,
                                             const float* __restrict__ sa_w,
                                             const float* __restrict__ sa_b) {
    __shared__ float gs[34][72];
    __shared__ float rs[4][8];
    __shared__ int s_last;
    const int b = blockIdx.z;
    const float* fr = frame + (size_t)b*3*HW;
    const int Bx = blockIdx.x*64, by0 = blockIdx.y*32;
    const int tid = threadIdx.x;

    float sr = 0.f, sg = 0.f, sb = 0.f;
    #pragma unroll
    for (int k = 0; k < 3; k++) {
        int i = tid + k*256;
        if (i < 34*18) {
            int r = i / 18, ci = i % 18;
            int y = min(max(by0 - 1 + r, 0), Hn-1);
            int xb = Bx - 4 + ci*4;
            float4 rv, gv, bv;
            if (xb >= 0 && xb <= Wn-4) {
                int o = y*Wn + xb;
                rv = *(const float4*)(fr + o);
                gv = *(const float4*)(fr + HW + o);
                bv = *(const float4*)(fr + 2*HW + o);
            } else {
                float* rp = (float*)&rv; float* gp = (float*)&gv; float* bp = (float*)&bv;
                #pragma unroll
                for (int j = 0; j < 4; j++) {
                    int x = min(max(xb + j, 0), Wn-1);
                    int o = y*Wn + x;
                    rp[j] = fr[o]; gp[j] = fr[HW+o]; bp[j] = fr[2*HW+o];
                }
            }
            float4 gr;
            gr.x = 0.299f*rv.x + 0.587f*gv.x + 0.114f*bv.x;
            gr.y = 0.299f*rv.y + 0.587f*gv.y + 0.114f*bv.y;
            gr.z = 0.299f*rv.z + 0.587f*gv.z + 0.114f*bv.z;
            gr.w = 0.299f*rv.w + 0.587f*gv.w + 0.114f*bv.w;
            *(float4*)&gs[r][ci*4] = gr;
            if (r >= 1 && r <= 32 && ci >= 1 && ci <= 16) {
                sr += rv.x+rv.y+rv.z+rv.w;
                sg += gv.x+gv.y+gv.z+gv.w;
                sb += bv.x+bv.y+bv.z+bv.w;
            }
        }
    }
    __syncthreads();

    int cmax = 0;
    {
        const int row = tid >> 3;
        const int P   = (tid & 7) * 8;
        const int ry  = row + 1;
        float t[16];
        float ctr[8];
        int m[8];

        #pragma unroll
        for (int q = 0; q < 4; q++) *(float4*)&t[q*4] = *(const float4*)&gs[ry][P + q*4];
        #pragma unroll
        for (int p = 0; p < 8; p++) { ctr[p] = t[4+p]; m[p] = 0; }
        #pragma unroll
        for (int p = 0; p < 8; p++) {
            m[p] |= ((int)(t[5+p] >= ctr[p]) << 2)
                  | ((int)(t[3+p] >= ctr[p]) << 6);
        }
        #pragma unroll
        for (int q = 0; q < 4; q++) *(float4*)&t[q*4] = *(const float4*)&gs[ry-1][P + q*4];
        #pragma unroll
        for (int p = 0; p < 8; p++) {
            m[p] |= ((int)(t[4+p] >= ctr[p]) << 0)
                  | ((int)(t[5+p] >= ctr[p]) << 1)
                  | ((int)(t[3+p] >= ctr[p]) << 7);
        }
        #pragma unroll
        for (int q = 0; q < 4; q++) *(float4*)&t[q*4] = *(const float4*)&gs[ry+1][P + q*4];
        #pragma unroll
        for (int p = 0; p < 8; p++) {
            m[p] |= ((int)(t[5+p] >= ctr[p]) << 3)
                  | ((int)(t[4+p] >= ctr[p]) << 4)
                  | ((int)(t[3+p] >= ctr[p]) << 5);
        }
        unsigned int clo = 0, chi = 0;
        #pragma unroll
        for (int p = 0; p < 8; p++) {
            int mm = m[p];
            int rot = ((mm << 1) | (mm >> 7)) & 255;
            int code = (__popc(mm ^ rot) <= 2) ? __popc(mm) : 9;
            cmax = max(cmax, code);
            if (p < 4) clo |= ((unsigned int)code) << (8*p);
            else       chi |= ((unsigned int)code) << (8*(p-4));
        }
        *(uint2*)&g_code[(size_t)b*HW + (by0+row)*Wn + Bx + P] = make_uint2(clo, chi);
    }

    #pragma unroll
    for (int off = 16; off; off >>= 1) {
        sr += __shfl_down_sync(0xffffffffu, sr, off);
        sg += __shfl_down_sync(0xffffffffu, sg, off);
        sb += __shfl_down_sync(0xffffffffu, sb, off);
        cmax = max(cmax, __shfl_down_sync(0xffffffffu, cmax, off));
    }
    int lane = tid & 31, warp = tid >> 5;
    if (lane == 0) { rs[0][warp] = sr; rs[1][warp] = sg; rs[2][warp] = sb; rs[3][warp] = (float)cmax; }
    __syncthreads();
    if (tid == 0) {
        float R=0, G=0, Bs=0, M=0;
        #pragma unroll
        for (int w = 0; w < 8; w++) { R += rs[0][w]; G += rs[1][w]; Bs += rs[2][w]; M = fmaxf(M, rs[3][w]); }
        int gbid = b*BLKS_PER_IMG + blockIdx.y*8 + blockIdx.x;
        g_partial[gbid*4+0] = R;
        g_partial[gbid*4+1] = G;
        g_partial[gbid*4+2] = Bs;
        g_partial[gbid*4+3] = M;
        __threadfence();
        int t = atomicAdd(&g_ctr, 1);
        s_last = (t == TOTAL_LBP_BLOCKS - 1);
    }
    __syncthreads();

    if (!s_last) return;

    if (tid < 28) {
        int c = tid / 7, ky = tid % 7;
        const float* w = sa_w + c*49 + ky*7;
        float w0=w[0], w1=w[1], w2=w[2], w3=w[3], w4=w[4], w5=w[5], w6=w[6];
        unsigned long long* d = &g_wpad[(c*7+ky)*8];
        d[0] = pk2(w0, w1); d[1] = pk2(w2, w3);
        d[2] = pk2(w4, w5); d[3] = pk2(w6, 0.f);
        d[4] = pk2(0.f, w0); d[5] = pk2(w1, w2);
        d[6] = pk2(w3, w4); d[7] = pk2(w5, w6);
    } else if (tid == 28) {
        g_wpad[224] = pk2(sa_b[0], 0.f);
    }

    for (int img = warp; img < Bn; img += 8) {
        float r = 0.f, g = 0.f, bl = 0.f, mx = 0.f;
        #pragma unroll
        for (int i = 0; i < 4; i++) {
            float4 v = *(const float4*)&g_partial[(img*BLKS_PER_IMG + lane + i*32)*4];
            r += v.x; g += v.y; bl += v.z; mx = fmaxf(mx, v.w);
        }
        #pragma unroll
        for (int off = 16; off; off >>= 1) {
            r  += __shfl_down_sync(0xffffffffu, r,  off);
            g  += __shfl_down_sync(0xffffffffu, g,  off);
            bl += __shfl_down_sync(0xffffffffu, bl, off);
            mx = fmaxf(mx, __shfl_down_sync(0xffffffffu, mx, off));
        }
        if (lane == 0) {
            const float inv = 1.0f / (float)HW;
            float rm = r*inv, gm = g*inv, bm = bl*inv;
            float p0 =  0.299f*rm + 0.587f*gm + 0.114f*bm;
            float p1 = -0.147f*rm - 0.289f*gm + 0.436f*bm;
            float p2 =  0.615f*rm - 0.515f*gm - 0.100f*bm;
            float h0 = fmaxf(p0*ca_w1[0] + p1*ca_w1[1] + p2*ca_w1[2], 0.f);
            float h1 = fmaxf(p0*ca_w1[3] + p1*ca_w1[4] + p2*ca_w1[5], 0.f);
            float h2 = fmaxf(p0*ca_w1[6] + p1*ca_w1[7] + p2*ca_w1[8], 0.f);
            #pragma unroll
            for (int k = 0; k < 3; k++) {
                float z = h0*ca_w2[k*3] + h1*ca_w2[k*3+1] + h2*ca_w2[k*3+2];
                g_scale[img*3+k] = 1.0f / (1.0f + expf(-z));
            }
            g_invmx[img] = 1.0f / mx;
        }
    }
    __syncthreads();
    if (tid == 0) g_ctr = 0;
}

// ---------------- K3 (fused): conv7x7 + mask + strength + watermark + RGB --
// Tile 64x32, 256 threads, thread = 4x2 outputs (R11 layout, coalesced LDS).
// Weights hoisted into registers per channel (LDC ratio 1:8 vs FFMA2).
__global__ void __launch_bounds__(256) k_mask(const float* __restrict__ frame,
                       const int* __restrict__ wm, int L,
                       float* __restrict__ out,
                       float* __restrict__ maskout) {
    __shared__ float gs[4][38][72];     // 43.8 kB
    const int b = blockIdx.z;
    const int tid = threadIdx.x;
    const int warp = tid >> 5, lane = tid & 31;
    const int wx = warp & 1, wy = warp >> 1;
    const int lx = lane & 7, ly = lane >> 3;

    const float invmx = g_invmx[b];
    const float* fr = frame + (size_t)b*3*HW;
    const unsigned char* cp = g_code + (size_t)b*HW;
    const int Bx = blockIdx.x*64;
    const int y0 = blockIdx.y*32 - 3;

    #pragma unroll
    for (int k = 0; k < 3; k++) {
        int i = tid + k*256;
        if (i < 38*18) {
            int r = i / 18, ci = i % 18;
            int y = y0 + r;
            int xb = Bx - 4 + ci*4;
            bool yin = (unsigned)y < (unsigned)Hn;
            float4 rv, gv, bv, cv;
            if (yin && xb >= 0 && xb <= Wn-4) {
                int o = y*Wn + xb;
                rv = *(const float4*)(fr + o);
                gv = *(const float4*)(fr + HW + o);
                bv = *(const float4*)(fr + 2*HW + o);
                unsigned int cw = *(const unsigned int*)(cp + o);
                cv.x = (float)(cw & 255u)*invmx;
                cv.y = (float)((cw >> 8) & 255u)*invmx;
                cv.z = (float)((cw >> 16) & 255u)*invmx;
                cv.w = (float)(cw >> 24)*invmx;
            } else {
                float* rp = (float*)&rv; float* gp = (float*)&gv;
                float* bp = (float*)&bv; float* qp = (float*)&cv;
                #pragma unroll
                for (int j = 0; j < 4; j++) {
                    int x = xb + j;
                    bool in = yin && (unsigned)x < (unsigned)Wn;
                    int o = y*Wn + x;
                    rp[j] = in ? fr[o]              : 0.f;
                    gp[j] = in ? fr[HW+o]           : 0.f;
                    bp[j] = in ? fr[2*HW+o]         : 0.f;
                    qp[j] = in ? (float)cp[o]*invmx : 0.f;
                }
            }
            *(float4*)&gs[0][r][ci*4] = rv;
            *(float4*)&gs[1][r][ci*4] = gv;
            *(float4*)&gs[2][r][ci*4] = bv;
            *(float4*)&gs[3][r][ci*4] = cv;
        }
    }
    __syncthreads();

    const int x4  = wx*32 + lx*4;   // tile col base
    const int ry0 = wy*8 + ly*2;    // tile row base

    unsigned long long acc[2][4];
    {
        unsigned long long binit = c_wp[224];
        #pragma unroll
        for (int o = 0; o < 2; o++)
            #pragma unroll
            for (int j = 0; j < 4; j++) acc[o][j] = binit;
    }

    // window for output u starts at col u+1 (odd): j0/j2 use Wo, j1/j3 use We
    #pragma unroll 1
    for (int c = 0; c < 4; c++) {
        // hoist this channel's weight pairs into registers (constant indices only)
        ulonglong2 W[7][4];
        #pragma unroll
        for (int ky = 0; ky < 7; ky++) {
            const ulonglong2* Wp = (const ulonglong2*)&c_wp[(c*7 + ky)*8];
            W[ky][0] = Wp[0];   // we01
            W[ky][1] = Wp[1];   // we23
            W[ky][2] = Wp[2];   // wo01
            W[ky][3] = Wp[3];   // wo23
        }
        #pragma unroll
        for (int rr = 0; rr < 8; rr++) {
            const float* row = &gs[c][ry0 + rr][x4];
            ulonglong2 pA = *(const ulonglong2*)row;
            ulonglong2 pB = *(const ulonglong2*)(row + 4);
            ulonglong2 pC = *(const ulonglong2*)(row + 8);
            unsigned long long P0 = pA.x, P1 = pA.y, P2 = pB.x,
                               P3 = pB.y, P4 = pC.x, P5 = pC.y;
            #pragma unroll
            for (int ky = 0; ky < 7; ky++) {
                const int o = rr - ky;
                if (o < 0 || o > 1) continue;
                ulonglong2 we01 = W[ky][0];
                ulonglong2 we23 = W[ky][1];
                ulonglong2 wo01 = W[ky][2];
                ulonglong2 wo23 = W[ky][3];
                acc[o][0] = ffma2(P0, wo01.x, ffma2(P1, wo01.y,
                            ffma2(P2, wo23.x, ffma2(P3, wo23.y, acc[o][0]))));
                acc[o][1] = ffma2(P1, we01.x, ffma2(P2, we01.y,
                            ffma2(P3, we23.x, ffma2(P4, we23.y, acc[o][1]))));
                acc[o][2] = ffma2(P1, wo01.x, ffma2(P2, wo01.y,
                            ffma2(P3, wo23.x, ffma2(P4, wo23.y, acc[o][2]))));
                acc[o][3] = ffma2(P2, we01.x, ffma2(P3, we01.y,
                            ffma2(P4, we23.x, ffma2(P5, we23.y, acc[o][3]))));
            }
        }
    }

    float mval[2][4];
    float sum8 = 0.f;
    #pragma unroll
    for (int o = 0; o < 2; o++)
        #pragma unroll
        for (int j = 0; j < 4; j++) {
            float lo, hi; unpk2(acc[o][j], lo, hi);
            float m = 1.f/(1.f + __expf(-(lo + hi)));
            mval[o][j] = m;
            sum8 += m;
        }
    // 8x8 block = lx pair (xor 1) x 4 ly groups (xor 8, xor 16)
    sum8 += __shfl_xor_sync(0xffffffffu, sum8, 1);
    sum8 += __shfl_xor_sync(0xffffffffu, sum8, 8);
    sum8 += __shfl_xor_sync(0xffffffffu, sum8, 16);
    const float st = sum8 * (1.f/64.f);

    const int gx0 = Bx + x4;
    const int gy0 = blockIdx.y*32 + ry0;
    const int bxb = gx0 >> 3, byb = gy0 >> 3;
    const int widx = (byb*NBLK + bxb) % L;
    const float delta = 0.05f * st * (2.f*(float)wm[widx] - 1.f);
    const float s0 = g_scale[b*3], s1 = g_scale[b*3+1], s2 = g_scale[b*3+2];
    const int l0 = gx0 & 7;
    float d3v0 = c_d3[l0], d3v1 = c_d3[l0+1], d3v2 = c_d3[l0+2], d3v3 = c_d3[l0+3];

    float* outp = out + (size_t)b*3*HW;
    float* mp   = maskout + (size_t)b*HW;
    #pragma unroll
    for (int o = 0; o < 2; o++) {
        const int gy = gy0 + o;
        const int sy = ry0 + o + 3;
        const float ddi = delta * c_d4[gy & 7];
        float ro[4], go[4], bo[4];
        #pragma unroll
        for (int j = 0; j < 4; j++) {
            float rr = gs[0][sy][x4+4+j];
            float gg = gs[1][sy][x4+4+j];
            float bb = gs[2][sy][x4+4+j];
            float yv =  0.299f*rr + 0.587f*gg + 0.114f*bb;
            float uu = -0.147f*rr - 0.289f*gg + 0.436f*bb;
            float vv =  0.615f*rr - 0.515f*gg - 0.100f*bb;
            float d3j = (j==0)?d3v0:(j==1)?d3v1:(j==2)?d3v2:d3v3;
            float yw = yv*s0 + ddi*d3j;
            float uw = uu*s1, vw = vv*s2;
            ro[j] = yw + 1.14f*vw;
            go[j] = yw - 0.395f*uw - 0.581f*vw;
            bo[j] = yw + 2.032f*uw;
        }
        size_t ob = (size_t)gy*Wn + gx0;
        *(float4*)&outp[ob]        = make_float4(ro[0], ro[1], ro[2], ro[3]);
        *(float4*)&outp[HW + ob]   = make_float4(go[0], go[1], go[2], go[3]);
        *(float4*)&outp[2*HW + ob] = make_float4(bo[0], bo[1], bo[2], bo[3]);
        *(float4*)&mp[ob] = make_float4(mval[o][0], mval[o][1], mval[o][2], mval[o][3]);
    }
}

// ---------------- launch ----------------------------------------------------
extern "C" void kernel_launch(void* const* d_in, const int* in_sizes, int n_in,
                              void* d_out, int out_size) {
    const float* frame = (const float*)d_in[0];
    const int*   wm    = (const int*)d_in[1];
    const float* sa_w  = (const float*)d_in[2];
    const float* sa_b  = (const float*)d_in[3];
    const float* ca_w1 = (const float*)d_in[4];
    const float* ca_w2 = (const float*)d_in[5];
    const int L = in_sizes[1];
    float* out = (float*)d_out;
    float* maskout = out + (size_t)Bn*3*HW;

    k_lbp<<<dim3(8, 16, Bn), 256>>>(frame, ca_w1, ca_w2, sa_w, sa_b);

    void* src = nullptr;
    cudaGetSymbolAddress(&src, g_wpad);
    cudaMemcpyToSymbolAsync(c_wp, src, 225*sizeof(unsigned long long), 0,
                            cudaMemcpyDeviceToDevice, 0);

    k_mask<<<dim3(8, 16, Bn), 256>>>(frame, wm, L, out, maskout);
}

// round 16
// speedup vs baseline: 1.7600x; 1.7600x over previous
#include <cuda_runtime.h>
#include <math.h>

#define Bn 16
#define Hn 512
#define Wn 512
#define HW (Hn*Wn)
#define NBLK 64
#define BLKS_PER_IMG 128
#define TOTAL_LBP_BLOCKS (8*16*Bn)

// ---------------- scratch ----------------
__device__ unsigned char g_code[(size_t)Bn*HW];
__device__ float g_partial[Bn*BLKS_PER_IMG*4];   // r,g,b,maxcode per 64x32 tile
__device__ float g_scale[Bn*3];
__device__ float g_invmx[Bn];
__device__ unsigned long long g_wpad[225];       // padded weight pairs + bias
__device__ int g_ctr;                            // last-block ticket (reset each run)

__constant__ unsigned long long c_wp[225];       // [(c*7+ky)*8 + j], [224]=bias
__constant__ float c_d4[8] = { 0.35355339f,-0.35355339f,-0.35355339f, 0.35355339f,
                               0.35355339f,-0.35355339f,-0.35355339f, 0.35355339f };
__constant__ float c_d3[8] = { 0.41573481f,-0.09754516f,-0.49039264f,-0.27778512f,
                               0.27778512f, 0.49039264f, 0.09754516f,-0.41573481f };

// ---- packed f32x2 helpers ----
__device__ __forceinline__ unsigned long long pk2(float lo, float hi) {
    unsigned long long d;
    asm("mov.b64 %0, {%1, %2};" : "=l"(d) : "f"(lo), "f"(hi));
    return d;
}
__device__ __forceinline__ unsigned long long ffma2(unsigned long long a,
                                                    unsigned long long b,
                                                    unsigned long long c) {
    unsigned long long d;
    asm("fma.rn.f32x2 %0, %1, %2, %3;" : "=l"(d) : "l"(a), "l"(b), "l"(c));
    return d;
}
__device__ __forceinline__ void unpk2(unsigned long long v, float& lo, float& hi) {
    asm("mov.b64 {%0, %1}, %2;" : "=f"(lo), "=f"(hi) : "l"(v));
}

// ---------------- K1: gray + LBP + partials, fused final reduction ---------
// 256 threads, 64x32 tile, grid (8,16,B). smem col c <-> x = bx*64-4+c.
__global__ void __launch_bounds__(256) k_lbp(const float* __restrict__ frame,
                                             const float* __restrict__ ca_w1,
                                             const float* __restrict__ ca_w2,
                                             const float* __restrict__ sa_w,
                                             const float* __restrict__ sa_b) {
    __shared__ float gs[34][72];
    __shared__ float rs[4][8];
    __shared__ int s_last;
    const int b = blockIdx.z;
    const float* fr = frame + (size_t)b*3*HW;
    const int Bx = blockIdx.x*64, by0 = blockIdx.y*32;
    const int tid = threadIdx.x;

    float sr = 0.f, sg = 0.f, sb = 0.f;
    #pragma unroll
    for (int k = 0; k < 3; k++) {
        int i = tid + k*256;
        if (i < 34*18) {
            int r = i / 18, ci = i % 18;
            int y = min(max(by0 - 1 + r, 0), Hn-1);
            int xb = Bx - 4 + ci*4;
            float4 rv, gv, bv;
            if (xb >= 0 && xb <= Wn-4) {
                int o = y*Wn + xb;
                rv = *(const float4*)(fr + o);
                gv = *(const float4*)(fr + HW + o);
                bv = *(const float4*)(fr + 2*HW + o);
            } else {
                float* rp = (float*)&rv; float* gp = (float*)&gv; float* bp = (float*)&bv;
                #pragma unroll
                for (int j = 0; j < 4; j++) {
                    int x = min(max(xb + j, 0), Wn-1);
                    int o = y*Wn + x;
                    rp[j] = fr[o]; gp[j] = fr[HW+o]; bp[j] = fr[2*HW+o];
                }
            }
            float4 gr;
            gr.x = 0.299f*rv.x + 0.587f*gv.x + 0.114f*bv.x;
            gr.y = 0.299f*rv.y + 0.587f*gv.y + 0.114f*bv.y;
            gr.z = 0.299f*rv.z + 0.587f*gv.z + 0.114f*bv.z;
            gr.w = 0.299f*rv.w + 0.587f*gv.w + 0.114f*bv.w;
            *(float4*)&gs[r][ci*4] = gr;
            if (r >= 1 && r <= 32 && ci >= 1 && ci <= 16) {
                sr += rv.x+rv.y+rv.z+rv.w;
                sg += gv.x+gv.y+gv.z+gv.w;
                sb += bv.x+bv.y+bv.z+bv.w;
            }
        }
    }
    __syncthreads();

    int cmax = 0;
    {
        const int row = tid >> 3;
        const int P   = (tid & 7) * 8;
        const int ry  = row + 1;
        float t[16];
        float ctr[8];
        int m[8];

        #pragma unroll
        for (int q = 0; q < 4; q++) *(float4*)&t[q*4] = *(const float4*)&gs[ry][P + q*4];
        #pragma unroll
        for (int p = 0; p < 8; p++) { ctr[p] = t[4+p]; m[p] = 0; }
        #pragma unroll
        for (int p = 0; p < 8; p++) {
            m[p] |= ((int)(t[5+p] >= ctr[p]) << 2)
                  | ((int)(t[3+p] >= ctr[p]) << 6);
        }
        #pragma unroll
        for (int q = 0; q < 4; q++) *(float4*)&t[q*4] = *(const float4*)&gs[ry-1][P + q*4];
        #pragma unroll
        for (int p = 0; p < 8; p++) {
            m[p] |= ((int)(t[4+p] >= ctr[p]) << 0)
                  | ((int)(t[5+p] >= ctr[p]) << 1)
                  | ((int)(t[3+p] >= ctr[p]) << 7);
        }
        #pragma unroll
        for (int q = 0; q < 4; q++) *(float4*)&t[q*4] = *(const float4*)&gs[ry+1][P + q*4];
        #pragma unroll
        for (int p = 0; p < 8; p++) {
            m[p] |= ((int)(t[5+p] >= ctr[p]) << 3)
                  | ((int)(t[4+p] >= ctr[p]) << 4)
                  | ((int)(t[3+p] >= ctr[p]) << 5);
        }
        unsigned int clo = 0, chi = 0;
        #pragma unroll
        for (int p = 0; p < 8; p++) {
            int mm = m[p];
            int rot = ((mm << 1) | (mm >> 7)) & 255;
            int code = (__popc(mm ^ rot) <= 2) ? __popc(mm) : 9;
            cmax = max(cmax, code);
            if (p < 4) clo |= ((unsigned int)code) << (8*p);
            else       chi |= ((unsigned int)code) << (8*(p-4));
        }
        *(uint2*)&g_code[(size_t)b*HW + (by0+row)*Wn + Bx + P] = make_uint2(clo, chi);
    }

    #pragma unroll
    for (int off = 16; off; off >>= 1) {
        sr += __shfl_down_sync(0xffffffffu, sr, off);
        sg += __shfl_down_sync(0xffffffffu, sg, off);
        sb += __shfl_down_sync(0xffffffffu, sb, off);
        cmax = max(cmax, __shfl_down_sync(0xffffffffu, cmax, off));
    }
    int lane = tid & 31, warp = tid >> 5;
    if (lane == 0) { rs[0][warp] = sr; rs[1][warp] = sg; rs[2][warp] = sb; rs[3][warp] = (float)cmax; }
    __syncthreads();
    if (tid == 0) {
        float R=0, G=0, Bs=0, M=0;
        #pragma unroll
        for (int w = 0; w < 8; w++) { R += rs[0][w]; G += rs[1][w]; Bs += rs[2][w]; M = fmaxf(M, rs[3][w]); }
        int gbid = b*BLKS_PER_IMG + blockIdx.y*8 + blockIdx.x;
        g_partial[gbid*4+0] = R;
        g_partial[gbid*4+1] = G;
        g_partial[gbid*4+2] = Bs;
        g_partial[gbid*4+3] = M;
        __threadfence();
        int t = atomicAdd(&g_ctr, 1);
        s_last = (t == TOTAL_LBP_BLOCKS - 1);
    }
    __syncthreads();

    if (!s_last) return;

    if (tid < 28) {
        int c = tid / 7, ky = tid % 7;
        const float* w = sa_w + c*49 + ky*7;
        float w0=w[0], w1=w[1], w2=w[2], w3=w[3], w4=w[4], w5=w[5], w6=w[6];
        unsigned long long* d = &g_wpad[(c*7+ky)*8];
        d[0] = pk2(w0, w1); d[1] = pk2(w2, w3);
        d[2] = pk2(w4, w5); d[3] = pk2(w6, 0.f);
        d[4] = pk2(0.f, w0); d[5] = pk2(w1, w2);
        d[6] = pk2(w3, w4); d[7] = pk2(w5, w6);
    } else if (tid == 28) {
        g_wpad[224] = pk2(sa_b[0], 0.f);
    }

    for (int img = warp; img < Bn; img += 8) {
        float r = 0.f, g = 0.f, bl = 0.f, mx = 0.f;
        #pragma unroll
        for (int i = 0; i < 4; i++) {
            float4 v = *(const float4*)&g_partial[(img*BLKS_PER_IMG + lane + i*32)*4];
            r += v.x; g += v.y; bl += v.z; mx = fmaxf(mx, v.w);
        }
        #pragma unroll
        for (int off = 16; off; off >>= 1) {
            r  += __shfl_down_sync(0xffffffffu, r,  off);
            g  += __shfl_down_sync(0xffffffffu, g,  off);
            bl += __shfl_down_sync(0xffffffffu, bl, off);
            mx = fmaxf(mx, __shfl_down_sync(0xffffffffu, mx, off));
        }
        if (lane == 0) {
            const float inv = 1.0f / (float)HW;
            float rm = r*inv, gm = g*inv, bm = bl*inv;
            float p0 =  0.299f*rm + 0.587f*gm + 0.114f*bm;
            float p1 = -0.147f*rm - 0.289f*gm + 0.436f*bm;
            float p2 =  0.615f*rm - 0.515f*gm - 0.100f*bm;
            float h0 = fmaxf(p0*ca_w1[0] + p1*ca_w1[1] + p2*ca_w1[2], 0.f);
            float h1 = fmaxf(p0*ca_w1[3] + p1*ca_w1[4] + p2*ca_w1[5], 0.f);
            float h2 = fmaxf(p0*ca_w1[6] + p1*ca_w1[7] + p2*ca_w1[8], 0.f);
            #pragma unroll
            for (int k = 0; k < 3; k++) {
                float z = h0*ca_w2[k*3] + h1*ca_w2[k*3+1] + h2*ca_w2[k*3+2];
                g_scale[img*3+k] = 1.0f / (1.0f + expf(-z));
            }
            g_invmx[img] = 1.0f / mx;
        }
    }
    __syncthreads();
    if (tid == 0) g_ctr = 0;
}

// ---------------- K3 (fused): conv7x7 + mask + strength + watermark + RGB --
// Tile 64x32, 256 threads, thread = 4x2 outputs (R11 coalesced layout).
// Loop nest: (c, ky) loads 4 weight vectors once; inner o-loop reuses them.
__global__ void __launch_bounds__(256) k_mask(const float* __restrict__ frame,
                       const int* __restrict__ wm, int L,
                       float* __restrict__ out,
                       float* __restrict__ maskout) {
    __shared__ float gs[4][38][72];     // 43.8 kB
    const int b = blockIdx.z;
    const int tid = threadIdx.x;
    const int warp = tid >> 5, lane = tid & 31;
    const int wx = warp & 1, wy = warp >> 1;
    const int lx = lane & 7, ly = lane >> 3;

    const float invmx = g_invmx[b];
    const float* fr = frame + (size_t)b*3*HW;
    const unsigned char* cp = g_code + (size_t)b*HW;
    const int Bx = blockIdx.x*64;
    const int y0 = blockIdx.y*32 - 3;

    #pragma unroll
    for (int k = 0; k < 3; k++) {
        int i = tid + k*256;
        if (i < 38*18) {
            int r = i / 18, ci = i % 18;
            int y = y0 + r;
            int xb = Bx - 4 + ci*4;
            bool yin = (unsigned)y < (unsigned)Hn;
            float4 rv, gv, bv, cv;
            if (yin && xb >= 0 && xb <= Wn-4) {
                int o = y*Wn + xb;
                rv = *(const float4*)(fr + o);
                gv = *(const float4*)(fr + HW + o);
                bv = *(const float4*)(fr + 2*HW + o);
                unsigned int cw = *(const unsigned int*)(cp + o);
                cv.x = (float)(cw & 255u)*invmx;
                cv.y = (float)((cw >> 8) & 255u)*invmx;
                cv.z = (float)((cw >> 16) & 255u)*invmx;
                cv.w = (float)(cw >> 24)*invmx;
            } else {
                float* rp = (float*)&rv; float* gp = (float*)&gv;
                float* bp = (float*)&bv; float* qp = (float*)&cv;
                #pragma unroll
                for (int j = 0; j < 4; j++) {
                    int x = xb + j;
                    bool in = yin && (unsigned)x < (unsigned)Wn;
                    int o = y*Wn + x;
                    rp[j] = in ? fr[o]              : 0.f;
                    gp[j] = in ? fr[HW+o]           : 0.f;
                    bp[j] = in ? fr[2*HW+o]         : 0.f;
                    qp[j] = in ? (float)cp[o]*invmx : 0.f;
                }
            }
            *(float4*)&gs[0][r][ci*4] = rv;
            *(float4*)&gs[1][r][ci*4] = gv;
            *(float4*)&gs[2][r][ci*4] = bv;
            *(float4*)&gs[3][r][ci*4] = cv;
        }
    }
    __syncthreads();

    const int x4  = wx*32 + lx*4;   // tile col base
    const int ry0 = wy*8 + ly*2;    // tile row base

    unsigned long long acc[2][4];
    {
        unsigned long long binit = c_wp[224];
        #pragma unroll
        for (int o = 0; o < 2; o++)
            #pragma unroll
            for (int j = 0; j < 4; j++) acc[o][j] = binit;
    }

    // window for output u starts at col u+1 (odd): j0/j2 use Wo, j1/j3 use We
    #pragma unroll 1
    for (int c = 0; c < 4; c++) {
        #pragma unroll
        for (int ky = 0; ky < 7; ky++) {
            const ulonglong2* Wp = (const ulonglong2*)&c_wp[(c*7 + ky)*8];
            const ulonglong2 we01 = Wp[0];
            const ulonglong2 we23 = Wp[1];
            const ulonglong2 wo01 = Wp[2];
            const ulonglong2 wo23 = Wp[3];
            #pragma unroll
            for (int o = 0; o < 2; o++) {
                const float* row = &gs[c][ry0 + o + ky][x4];
                ulonglong2 pA = *(const ulonglong2*)row;
                ulonglong2 pB = *(const ulonglong2*)(row + 4);
                ulonglong2 pC = *(const ulonglong2*)(row + 8);
                unsigned long long P0 = pA.x, P1 = pA.y, P2 = pB.x,
                                   P3 = pB.y, P4 = pC.x, P5 = pC.y;
                acc[o][0] = ffma2(P0, wo01.x, ffma2(P1, wo01.y,
                            ffma2(P2, wo23.x, ffma2(P3, wo23.y, acc[o][0]))));
                acc[o][1] = ffma2(P1, we01.x, ffma2(P2, we01.y,
                            ffma2(P3, we23.x, ffma2(P4, we23.y, acc[o][1]))));
                acc[o][2] = ffma2(P1, wo01.x, ffma2(P2, wo01.y,
                            ffma2(P3, wo23.x, ffma2(P4, wo23.y, acc[o][2]))));
                acc[o][3] = ffma2(P2, we01.x, ffma2(P3, we01.y,
                            ffma2(P4, we23.x, ffma2(P5, we23.y, acc[o][3]))));
            }
        }
    }

    float mval[2][4];
    float sum8 = 0.f;
    #pragma unroll
    for (int o = 0; o < 2; o++)
        #pragma unroll
        for (int j = 0; j < 4; j++) {
            float lo, hi; unpk2(acc[o][j], lo, hi);
            float m = 1.f/(1.f + __expf(-(lo + hi)));
            mval[o][j] = m;
            sum8 += m;
        }
    // 8x8 block = lx pair (xor 1) x 4 ly groups (xor 8, xor 16)
    sum8 += __shfl_xor_sync(0xffffffffu, sum8, 1);
    sum8 += __shfl_xor_sync(0xffffffffu, sum8, 8);
    sum8 += __shfl_xor_sync(0xffffffffu, sum8, 16);
    const float st = sum8 * (1.f/64.f);

    const int gx0 = Bx + x4;
    const int gy0 = blockIdx.y*32 + ry0;
    const int bxb = gx0 >> 3, byb = gy0 >> 3;
    const int widx = (byb*NBLK + bxb) % L;
    const float delta = 0.05f * st * (2.f*(float)wm[widx] - 1.f);
    const float s0 = g_scale[b*3], s1 = g_scale[b*3+1], s2 = g_scale[b*3+2];
    const int l0 = gx0 & 7;
    float d3v0 = c_d3[l0], d3v1 = c_d3[l0+1], d3v2 = c_d3[l0+2], d3v3 = c_d3[l0+3];

    float* outp = out + (size_t)b*3*HW;
    float* mp   = maskout + (size_t)b*HW;
    #pragma unroll
    for (int o = 0; o < 2; o++) {
        const int gy = gy0 + o;
        const int sy = ry0 + o + 3;
        const float ddi = delta * c_d4[gy & 7];
        float ro[4], go[4], bo[4];
        #pragma unroll
        for (int j = 0; j < 4; j++) {
            float rr = gs[0][sy][x4+4+j];
            float gg = gs[1][sy][x4+4+j];
            float bb = gs[2][sy][x4+4+j];
            float yv =  0.299f*rr + 0.587f*gg + 0.114f*bb;
            float uu = -0.147f*rr - 0.289f*gg + 0.436f*bb;
            float vv =  0.615f*rr - 0.515f*gg - 0.100f*bb;
            float d3j = (j==0)?d3v0:(j==1)?d3v1:(j==2)?d3v2:d3v3;
            float yw = yv*s0 + ddi*d3j;
            float uw = uu*s1, vw = vv*s2;
            ro[j] = yw + 1.14f*vw;
            go[j] = yw - 0.395f*uw - 0.581f*vw;
            bo[j] = yw + 2.032f*uw;
        }
        size_t ob = (size_t)gy*Wn + gx0;
        *(float4*)&outp[ob]        = make_float4(ro[0], ro[1], ro[2], ro[3]);
        *(float4*)&outp[HW + ob]   = make_float4(go[0], go[1], go[2], go[3]);
        *(float4*)&outp[2*HW + ob] = make_float4(bo[0], bo[1], bo[2], bo[3]);
        *(float4*)&mp[ob] = make_float4(mval[o][0], mval[o][1], mval[o][2], mval[o][3]);
    }
}

// ---------------- launch ----------------------------------------------------
extern "C" void kernel_launch(void* const* d_in, const int* in_sizes, int n_in,
                              void* d_out, int out_size) {
    const float* frame = (const float*)d_in[0];
    const int*   wm    = (const int*)d_in[1];
    const float* sa_w  = (const float*)d_in[2];
    const float* sa_b  = (const float*)d_in[3];
    const float* ca_w1 = (const float*)d_in[4];
    const float* ca_w2 = (const float*)d_in[5];
    const int L = in_sizes[1];
    float* out = (float*)d_out;
    float* maskout = out + (size_t)Bn*3*HW;

    k_lbp<<<dim3(8, 16, Bn), 256>>>(frame, ca_w1, ca_w2, sa_w, sa_b);

    void* src = nullptr;
    cudaGetSymbolAddress(&src, g_wpad);
    cudaMemcpyToSymbolAsync(c_wp, src, 225*sizeof(unsigned long long), 0,
                            cudaMemcpyDeviceToDevice, 0);

    k_mask<<<dim3(8, 16, Bn), 256>>>(frame, wm, L, out, maskout);
}